// round 12
// baseline (speedup 1.0000x reference)
#include <cuda_runtime.h>
#include <cuda_fp16.h>
#include <cstdint>

// ---------------- problem constants ----------------
#define NQ   50000
#define NMS  50000
#define NH   32
#define NK   15
#define NC   64
#define ND   64
#define KPAD 50048          // NQ padded to multiple of 128
#define KC2  1024           // 64 channels * 16 (k padded 15->16)

// scratch: SINGLE fp16 plane of weighted[n][c*16+k] (normalization folded in)
__device__ __half g_a[(size_t)KPAD * KC2];           // ~102 MB
__device__ uint2  g_bfrag[64 * 8 * 32];              // B fp16 fragments, 128 KB
__device__ float  g_flag[NMS];                       // rowsum>0 flags

// ---------------- helpers ----------------
__device__ __forceinline__ unsigned long long ffma2(unsigned long long a,
                                                    unsigned long long b,
                                                    unsigned long long c) {
    unsigned long long d;
    asm("fma.rn.f32x2 %0, %1, %2, %3;" : "=l"(d) : "l"(a), "l"(b), "l"(c));
    return d;
}
__device__ __forceinline__ unsigned long long splat2(float v) {
    unsigned long long d;
    asm("mov.b64 %0, {%1, %1};" : "=l"(d) : "f"(v));
    return d;
}
__device__ __forceinline__ float2 unpack2(unsigned long long v) {
    float2 r;
    asm("mov.b64 {%0, %1}, %2;" : "=f"(r.x), "=f"(r.y) : "l"(v));
    return r;
}
__device__ __forceinline__ unsigned long long mul2(unsigned long long a,
                                                   unsigned long long b) {
    unsigned long long d;
    asm("mul.rn.f32x2 %0, %1, %2;" : "=l"(d) : "l"(a), "l"(b));
    return d;
}
// pack fp16x2: low half = x (first elem in memory), high = y
__device__ __forceinline__ uint32_t pack_f16x2(float x, float y) {
    uint32_t r;
    asm("cvt.rn.f16x2.f32 %0, %1, %2;" : "=r"(r) : "f"(y), "f"(x));
    return r;
}
__device__ __forceinline__ uint32_t smem_u32(const void* p) {
    uint32_t a;
    asm("{ .reg .u64 t; cvta.to.shared.u64 t, %1; cvt.u32.u64 %0, t; }" : "=r"(a) : "l"(p));
    return a;
}
__device__ __forceinline__ void cp16(uint32_t dst, const void* src) {
    asm volatile("cp.async.cg.shared.global [%0], [%1], 16;" :: "r"(dst), "l"(src));
}
#define CP_COMMIT() asm volatile("cp.async.commit_group;" ::: "memory")
#define CP_WAIT0()  asm volatile("cp.async.wait_group 0;" ::: "memory")
#define CP_WAIT1()  asm volatile("cp.async.wait_group 1;" ::: "memory")
#define CP_WAIT2()  asm volatile("cp.async.wait_group 2;" ::: "memory")
#define SWZ(o) ((o) ^ (((o) >> 3) & 0x70))

__device__ __forceinline__ void ldsm4(uint32_t& r0, uint32_t& r1, uint32_t& r2,
                                      uint32_t& r3, uint32_t addr) {
    asm volatile("ldmatrix.sync.aligned.m8n8.x4.shared.b16 {%0,%1,%2,%3}, [%4];"
        : "=r"(r0), "=r"(r1), "=r"(r2), "=r"(r3) : "r"(addr));
}
__device__ __forceinline__ void mma16816(float* d, const uint32_t* a,
                                         uint32_t b0, uint32_t b1) {
    asm volatile(
        "mma.sync.aligned.m16n8k16.row.col.f32.f16.f16.f32 "
        "{%0,%1,%2,%3}, {%4,%5,%6,%7}, {%8,%9}, {%0,%1,%2,%3};"
        : "+f"(d[0]), "+f"(d[1]), "+f"(d[2]), "+f"(d[3])
        : "r"(a[0]), "r"(a[1]), "r"(a[2]), "r"(a[3]), "r"(b0), "r"(b1));
}

// =============================================================================
// prep A: validity flags f[m] = (sum_c x[m,c] > 0)
// =============================================================================
__global__ void __launch_bounds__(256) prep_flags(const float* __restrict__ x) {
    const int w = threadIdx.x >> 5, l = threadIdx.x & 31;
    const int r = blockIdx.x * 16 + w * 2 + (l >> 4);
    const float4 v = ((const float4*)(x + (size_t)r * NC))[l & 15];
    float s = v.x + v.y + v.z + v.w;
    #pragma unroll
    for (int o = 1; o < 16; o <<= 1) s += __shfl_xor_sync(0xffffffffu, s, o);
    if ((l & 15) == 0) g_flag[r] = (s > 0.0f) ? 1.0f : 0.0f;
}

// =============================================================================
// prep B: pack W into m16n8k16 B-fragment order (single fp16 plane).
//   B[kc][n] = W[k_kp][c][n],  kc = c*16 + k_kp  (k_kp==15 -> 0 pad)
// =============================================================================
__device__ __forceinline__ float wval(const float* W, int kc, int n) {
    const int k_kp = kc & 15, c = kc >> 4;
    return (k_kp < NK) ? W[((size_t)k_kp * NC + c) * ND + n] : 0.0f;
}
__global__ void __launch_bounds__(256) prep_w(const float* __restrict__ W) {
    const int g     = blockIdx.x * 256 + threadIdx.x;   // 64*8*32 = 16384
    const int lane  = g & 31;
    const int ntile = (g >> 5) & 7;
    const int kstep = g >> 8;                           // 0..63
    const int n  = ntile * 8 + (lane >> 2);
    const int kc = kstep * 16 + 2 * (lane & 3);
    g_bfrag[g] = make_uint2(
        pack_f16x2(wval(W, kc,     n), wval(W, kc + 1, n)),
        pack_f16x2(wval(W, kc + 8, n), wval(W, kc + 9, n)));
}

// =============================================================================
// Stage 1 (compaction + depth-4 register prefetch pipeline).
// One warp per query; 8 queries / 256-thread block.
// Phase A: lane = neighbor h; w[h][k]; dead neighbors dropped via ballot
//          compaction. ws pre-zeroed so pad slots (nact..nact_pad) are exact 0.
// Phase B: outer loop over 4-h blocks (nact padded to x4); inner static.
//          x values for block i are loaded during block i-1 into registers
//          (bx/by), giving ~1 full block (~200+ cyc) of load->use decoupling.
// =============================================================================
__global__ void __launch_bounds__(256) kpconv_stage1(
    const float* __restrict__ q_pts, const float* __restrict__ s_pts,
    const int*   __restrict__ nbi,   const float* __restrict__ x,
    const float* __restrict__ kp)
{
    __shared__ __align__(16) float ws[8][NH][16];   // 16 KB
    __shared__ int idxs[8][NH];
    const int warp = threadIdx.x >> 5;
    const int lane = threadIdx.x & 31;
    const int n    = blockIdx.x * 8 + warp;

    // ---- phase A: lane = neighbor h ----
    const int idx = __ldg(&nbi[n * NH + lane]);
    const float qx = q_pts[n*3+0], qy = q_pts[n*3+1], qz = q_pts[n*3+2];
    const float dx = __ldg(&s_pts[idx*3+0]) - qx;
    const float dy = __ldg(&s_pts[idx*3+1]) - qy;
    const float dz = __ldg(&s_pts[idx*3+2]) - qz;
    const float vf = __ldg(&g_flag[idx]);

    // zero-init this warp's ws + default idxs (pads become exact zeros)
    {
        float4* wz = (float4*)&ws[warp][lane][0];
        const float4 z = make_float4(0.f, 0.f, 0.f, 0.f);
        wz[0] = z; wz[1] = z; wz[2] = z; wz[3] = z;
        idxs[warp][lane] = idx;          // any valid index
    }

    float wk[16];
    bool anyw = false;
    #pragma unroll
    for (int k = 0; k < NK; k++) {
        const float ex = dx - kp[k*3+0];
        const float ey = dy - kp[k*3+1];
        const float ez = dz - kp[k*3+2];
        const float d2 = ex*ex + ey*ey + ez*ez;
        const float r  = __frsqrt_rn(fmaxf(d2, 1e-24f));
        const float w  = fmaxf(1.0f - (d2 * r) * (1.0f / 1.2f), 0.0f);
        wk[k] = w;
        anyw = anyw || (w > 0.0f);
    }
    wk[15] = 0.0f;

    const uint32_t amask = __ballot_sync(0xffffffffu, anyw);
    const int nact = __popc(amask);
    const int cnt  = __popc(__ballot_sync(0xffffffffu, vf > 0.0f));
    __syncwarp();   // zero-init complete before compaction overwrites
    if (anyw) {
        const int pos = __popc(amask & ((1u << lane) - 1u));
        #pragma unroll
        for (int k = 0; k < 16; k++) ws[warp][pos][k] = wk[k];
        idxs[warp][pos] = idx;
    }
    __syncwarp();

    // ---- phase B: depth-4 prefetch pipeline over padded active list ----
    const int npad = (nact + 3) & ~3;   // multiple of 4 (pads have w==0)
    unsigned long long a0[8], a1[8];
    #pragma unroll
    for (int j = 0; j < 8; j++) { a0[j] = 0ull; a1[j] = 0ull; }

    float bx[4], by[4];
    #pragma unroll
    for (int j = 0; j < 4; j++) {
        const int hp = (j < npad) ? j : 0;      // idxs always valid
        const float* xr = x + (size_t)idxs[warp][hp] * NC;
        bx[j] = __ldg(&xr[lane]);
        by[j] = __ldg(&xr[lane + 32]);
    }

    for (int hb = 0; hb < npad; hb += 4) {
        #pragma unroll
        for (int j = 0; j < 4; j++) {
            const unsigned long long xx0 = splat2(bx[j]);
            const unsigned long long xx1 = splat2(by[j]);
            // prefetch h = hb+j+4 (clamped; value unused past end)
            {
                const int hn = (hb + j + 4 < npad) ? hb + j + 4 : 0;
                const float* xr = x + (size_t)idxs[warp][hn] * NC;
                bx[j] = __ldg(&xr[lane]);
                by[j] = __ldg(&xr[lane + 32]);
            }
            const ulonglong2* wp = (const ulonglong2*)&ws[warp][hb + j][0];
            #pragma unroll
            for (int q = 0; q < 4; q++) {
                const ulonglong2 w2 = wp[q];
                a0[2*q+0] = ffma2(w2.x, xx0, a0[2*q+0]);
                a0[2*q+1] = ffma2(w2.y, xx0, a0[2*q+1]);
                a1[2*q+0] = ffma2(w2.x, xx1, a1[2*q+0]);
                a1[2*q+1] = ffma2(w2.y, xx1, a1[2*q+1]);
            }
        }
    }

    const float inv = 1.0f / (float)(cnt > 0 ? cnt : 1);
    const unsigned long long inv2 = splat2(inv);

    // ---- epilogue: single fp16 plane, 2x STG.128 per channel ----
    #pragma unroll
    for (int half = 0; half < 2; half++) {
        const int c = lane + half * 32;
        const unsigned long long* acc = half ? a1 : a0;
        uint32_t p[8];
        #pragma unroll
        for (int j = 0; j < 8; j++) {
            const float2 s = unpack2(mul2(acc[j], inv2));
            p[j] = pack_f16x2(s.x, s.y);
        }
        uint4* pa = (uint4*)(g_a + (size_t)n * KC2 + c * 16);
        pa[0] = make_uint4(p[0], p[1], p[2], p[3]);
        pa[1] = make_uint4(p[4], p[5], p[6], p[7]);
    }
}

// =============================================================================
// Stage 2 (v5): single fp16 product, 3-stage cp.async pipeline. BM=128.
// Smem per buffer: A 16K | Bfrag 8K = 24K; x3 = 72 KB -> 3 blocks/SM.
// =============================================================================
#define S2_THREADS 256
#define BUFB 24576
#define OFF_BF  16384
#define SM_TOT  (3 * BUFB)

__device__ __forceinline__ void s2_issue(uint32_t sb, int buf, int chunk, int tid,
                                         const char* Apl) {
    const uint32_t base = sb + buf * BUFB;
    #pragma unroll
    for (int i = 0; i < 4; i++) {                 // A: 128 rows x 128B
        const int ch  = i * S2_THREADS + tid;     // 0..1023
        const int rr  = ch >> 3;
        const int c16 = (ch & 7) * 16;
        const uint32_t d = SWZ((uint32_t)(rr * 128 + c16));
        cp16(base + d, Apl + (size_t)rr * 2048 + chunk * 128 + c16);
    }
    #pragma unroll
    for (int i = 0; i < 2; i++) {                 // B frags: 8 KB linear
        const int ch = i * S2_THREADS + tid;      // 0..511
        cp16(base + OFF_BF + ch * 16, (const char*)g_bfrag + ((size_t)chunk * 512 + ch) * 16);
    }
}

__global__ void __launch_bounds__(S2_THREADS) kpconv_stage2(float* __restrict__ out) {
    extern __shared__ __align__(1024) char smem[];
    const uint32_t sb = smem_u32(smem);
    const int tid  = threadIdx.x;
    const int wid  = tid >> 5;
    const int lane = tid & 31;
    const int n0   = blockIdx.x * 128;
    const int m0   = wid * 16;

    const char* Apl = (const char*)(g_a + (size_t)n0 * KC2);

    float d[8][4];
    #pragma unroll
    for (int t = 0; t < 8; t++)
        #pragma unroll
        for (int j = 0; j < 4; j++) d[t][j] = 0.0f;

    const uint32_t arow  = (uint32_t)(m0 + (lane & 15));
    const uint32_t ahalf = (uint32_t)((lane >> 4) * 16);   // bytes

    s2_issue(sb, 0, 0, tid, Apl);
    CP_COMMIT();
    s2_issue(sb, 1, 1, tid, Apl);
    CP_COMMIT();

    int buf = 0;
    for (int ch = 0; ch < 16; ch++) {
        if (ch + 2 < 16) {
            s2_issue(sb, (ch + 2) % 3, ch + 2, tid, Apl);
            CP_COMMIT();
            CP_WAIT2();
        } else if (ch + 1 < 16) {
            CP_WAIT1();
        } else {
            CP_WAIT0();
        }
        __syncthreads();

        const uint32_t base = sb + buf * BUFB;
        #pragma unroll
        for (int ks = 0; ks < 4; ks++) {
            const uint32_t aoff = SWZ(arow * 128 + (uint32_t)(ks * 32) + ahalf);
            uint32_t a[4];
            ldsm4(a[0], a[1], a[2], a[3], base + aoff);
            const uint32_t bbase = base + OFF_BF + (uint32_t)(ks * 8 * 32 + lane) * 8;
            #pragma unroll
            for (int nt = 0; nt < 8; nt++) {
                uint2 bf;
                asm volatile("ld.shared.v2.b32 {%0,%1}, [%2];"
                    : "=r"(bf.x), "=r"(bf.y)
                    : "r"(bbase + (uint32_t)(nt * 32 * 8)));
                mma16816(d[nt], a, bf.x, bf.y);
            }
        }
        __syncthreads();
        buf = (buf + 1 == 3) ? 0 : buf + 1;
    }

    const int r0 = n0 + m0 + (lane >> 2);
    const int r1 = r0 + 8;
    const int c0 = (lane & 3) * 2;
    #pragma unroll
    for (int nt = 0; nt < 8; nt++) {
        const int c = nt * 8 + c0;
        if (r0 < NQ) *(float2*)(out + (size_t)r0 * ND + c) = make_float2(d[nt][0], d[nt][1]);
        if (r1 < NQ) *(float2*)(out + (size_t)r1 * ND + c) = make_float2(d[nt][2], d[nt][3]);
    }
}

// =============================================================================
extern "C" void kernel_launch(void* const* d_in, const int* in_sizes, int n_in,
                              void* d_out, int out_size) {
    const float* q_pts = (const float*)d_in[0];
    const float* s_pts = (const float*)d_in[1];
    const int*   nbi   = (const int*)  d_in[2];
    const float* x     = (const float*)d_in[3];
    const float* kp    = (const float*)d_in[4];
    const float* W     = (const float*)d_in[5];
    float* out = (float*)d_out;

    cudaFuncSetAttribute(kpconv_stage2, cudaFuncAttributeMaxDynamicSharedMemorySize, SM_TOT);

    prep_flags<<<NMS / 16, 256>>>(x);
    prep_w<<<64, 256>>>(W);
    kpconv_stage1<<<NQ / 8, 256>>>(q_pts, s_pts, nbi, x, kp);
    kpconv_stage2<<<KPAD / 128, S2_THREADS, SM_TOT>>>(out);
}

// round 13
// speedup vs baseline: 1.0177x; 1.0177x over previous
#include <cuda_runtime.h>
#include <cuda_fp16.h>
#include <cstdint>

// ---------------- problem constants ----------------
#define NQ   50000
#define NMS  50000
#define NH   32
#define NK   15
#define NC   64
#define ND   64
#define KPAD 50048          // NQ padded to multiple of 128
#define KC2  1024           // 64 channels * 16 (k padded 15->16)

// scratch: SINGLE fp16 plane of weighted[n][c*16+k] (normalization folded in)
__device__ __half g_a[(size_t)KPAD * KC2];           // ~102 MB
__device__ __half g_x16[(size_t)NMS * NC];           // fp16 copy of x, 6.4 MB
__device__ uint2  g_bfrag[64 * 8 * 32];              // B fp16 fragments, 128 KB
__device__ float  g_flag[NMS];                       // rowsum>0 flags

// ---------------- helpers ----------------
__device__ __forceinline__ unsigned long long ffma2(unsigned long long a,
                                                    unsigned long long b,
                                                    unsigned long long c) {
    unsigned long long d;
    asm("fma.rn.f32x2 %0, %1, %2, %3;" : "=l"(d) : "l"(a), "l"(b), "l"(c));
    return d;
}
__device__ __forceinline__ unsigned long long splat2(float v) {
    unsigned long long d;
    asm("mov.b64 %0, {%1, %1};" : "=l"(d) : "f"(v));
    return d;
}
__device__ __forceinline__ float2 unpack2(unsigned long long v) {
    float2 r;
    asm("mov.b64 {%0, %1}, %2;" : "=f"(r.x), "=f"(r.y) : "l"(v));
    return r;
}
__device__ __forceinline__ unsigned long long mul2(unsigned long long a,
                                                   unsigned long long b) {
    unsigned long long d;
    asm("mul.rn.f32x2 %0, %1, %2;" : "=l"(d) : "l"(a), "l"(b));
    return d;
}
// pack fp16x2: low half = x (first elem in memory), high = y
__device__ __forceinline__ uint32_t pack_f16x2(float x, float y) {
    uint32_t r;
    asm("cvt.rn.f16x2.f32 %0, %1, %2;" : "=r"(r) : "f"(y), "f"(x));
    return r;
}
__device__ __forceinline__ uint32_t smem_u32(const void* p) {
    uint32_t a;
    asm("{ .reg .u64 t; cvta.to.shared.u64 t, %1; cvt.u32.u64 %0, t; }" : "=r"(a) : "l"(p));
    return a;
}
__device__ __forceinline__ void cp16(uint32_t dst, const void* src) {
    asm volatile("cp.async.cg.shared.global [%0], [%1], 16;" :: "r"(dst), "l"(src));
}
#define CP_COMMIT() asm volatile("cp.async.commit_group;" ::: "memory")
#define CP_WAIT0()  asm volatile("cp.async.wait_group 0;" ::: "memory")
#define CP_WAIT1()  asm volatile("cp.async.wait_group 1;" ::: "memory")
#define SWZ(o) ((o) ^ (((o) >> 3) & 0x70))

__device__ __forceinline__ void ldsm4(uint32_t& r0, uint32_t& r1, uint32_t& r2,
                                      uint32_t& r3, uint32_t addr) {
    asm volatile("ldmatrix.sync.aligned.m8n8.x4.shared.b16 {%0,%1,%2,%3}, [%4];"
        : "=r"(r0), "=r"(r1), "=r"(r2), "=r"(r3) : "r"(addr));
}
__device__ __forceinline__ void mma16816(float* d, const uint32_t* a,
                                         uint32_t b0, uint32_t b1) {
    asm volatile(
        "mma.sync.aligned.m16n8k16.row.col.f32.f16.f16.f32 "
        "{%0,%1,%2,%3}, {%4,%5,%6,%7}, {%8,%9}, {%0,%1,%2,%3};"
        : "+f"(d[0]), "+f"(d[1]), "+f"(d[2]), "+f"(d[3])
        : "r"(a[0]), "r"(a[1]), "r"(a[2]), "r"(a[3]), "r"(b0), "r"(b1));
}

// =============================================================================
// prep X: fp16 copy of x (halves stage1 gather sector traffic)
// =============================================================================
__global__ void __launch_bounds__(256) prep_x(const float* __restrict__ x) {
    const int i = blockIdx.x * 256 + threadIdx.x;   // grid covers NMS*NC/4
    const float4 v = ((const float4*)x)[i];
    ((uint2*)g_x16)[i] = make_uint2(pack_f16x2(v.x, v.y), pack_f16x2(v.z, v.w));
}

// =============================================================================
// prep A: validity flags f[m] = (sum_c x[m,c] > 0)
// =============================================================================
__global__ void __launch_bounds__(256) prep_flags(const float* __restrict__ x) {
    const int w = threadIdx.x >> 5, l = threadIdx.x & 31;
    const int r = blockIdx.x * 16 + w * 2 + (l >> 4);
    const float4 v = ((const float4*)(x + (size_t)r * NC))[l & 15];
    float s = v.x + v.y + v.z + v.w;
    #pragma unroll
    for (int o = 1; o < 16; o <<= 1) s += __shfl_xor_sync(0xffffffffu, s, o);
    if ((l & 15) == 0) g_flag[r] = (s > 0.0f) ? 1.0f : 0.0f;
}

// =============================================================================
// prep B: pack W into m16n8k16 B-fragment order (single fp16 plane).
//   B[kc][n] = W[k_kp][c][n],  kc = c*16 + k_kp  (k_kp==15 -> 0 pad)
// =============================================================================
__device__ __forceinline__ float wval(const float* W, int kc, int n) {
    const int k_kp = kc & 15, c = kc >> 4;
    return (k_kp < NK) ? W[((size_t)k_kp * NC + c) * ND + n] : 0.0f;
}
__global__ void __launch_bounds__(256) prep_w(const float* __restrict__ W) {
    const int g     = blockIdx.x * 256 + threadIdx.x;   // 64*8*32 = 16384
    const int lane  = g & 31;
    const int ntile = (g >> 5) & 7;
    const int kstep = g >> 8;                           // 0..63
    const int n  = ntile * 8 + (lane >> 2);
    const int kc = kstep * 16 + 2 * (lane & 3);
    g_bfrag[g] = make_uint2(
        pack_f16x2(wval(W, kc,     n), wval(W, kc + 1, n)),
        pack_f16x2(wval(W, kc + 8, n), wval(W, kc + 9, n)));
}

// =============================================================================
// Stage 1 (R11 shape + fp16 x gathers).
// One warp per query; 8 queries / 256-thread block.
// Phase A: lane = neighbor h; w[h][k]; dead neighbors dropped via ballot
//          compaction (warp-uniform loop bound, no divergence).
// Phase B: lane = channels (2*lane, 2*lane+1): ONE LDG.32 fp16x2 per x-row
//          per h (128B/row total — half the fp32 sector traffic);
//          16 f32x2 k-pair accumulators.
// =============================================================================
__global__ void __launch_bounds__(256) kpconv_stage1(
    const float* __restrict__ q_pts, const float* __restrict__ s_pts,
    const int*   __restrict__ nbi,   const float* __restrict__ kp)
{
    __shared__ __align__(16) float ws[8][NH][16];   // 16 KB
    __shared__ int idxs[8][NH];
    const int warp = threadIdx.x >> 5;
    const int lane = threadIdx.x & 31;
    const int n    = blockIdx.x * 8 + warp;

    // ---- phase A: lane = neighbor h ----
    const int idx = __ldg(&nbi[n * NH + lane]);
    const float qx = q_pts[n*3+0], qy = q_pts[n*3+1], qz = q_pts[n*3+2];
    const float dx = __ldg(&s_pts[idx*3+0]) - qx;
    const float dy = __ldg(&s_pts[idx*3+1]) - qy;
    const float dz = __ldg(&s_pts[idx*3+2]) - qz;
    const float vf = __ldg(&g_flag[idx]);

    float wk[16];
    bool anyw = false;
    #pragma unroll
    for (int k = 0; k < NK; k++) {
        const float ex = dx - kp[k*3+0];
        const float ey = dy - kp[k*3+1];
        const float ez = dz - kp[k*3+2];
        const float d2 = ex*ex + ey*ey + ez*ez;
        const float r  = __frsqrt_rn(fmaxf(d2, 1e-24f));
        const float w  = fmaxf(1.0f - (d2 * r) * (1.0f / 1.2f), 0.0f);
        wk[k] = w;
        anyw = anyw || (w > 0.0f);
    }
    wk[15] = 0.0f;

    const uint32_t amask = __ballot_sync(0xffffffffu, anyw);
    const int nact = __popc(amask);
    const int cnt  = __popc(__ballot_sync(0xffffffffu, vf > 0.0f));
    if (anyw) {
        const int pos = __popc(amask & ((1u << lane) - 1u));
        #pragma unroll
        for (int k = 0; k < 16; k++) ws[warp][pos][k] = wk[k];
        idxs[warp][pos] = idx;
    }
    __syncwarp();

    // ---- phase B: lane = channels (2*lane, 2*lane+1), active h only ----
    unsigned long long a0[8], a1[8];
    #pragma unroll
    for (int j = 0; j < 8; j++) { a0[j] = 0ull; a1[j] = 0ull; }

    #pragma unroll 4
    for (int h = 0; h < nact; h++) {
        const int ih = idxs[warp][h];
        const uint32_t xw = __ldg((const uint32_t*)(g_x16 + (size_t)ih * NC) + lane);
        const float2 xf = __half22float2(*(const __half2*)&xw);
        const unsigned long long xx0 = splat2(xf.x);
        const unsigned long long xx1 = splat2(xf.y);
        const ulonglong2* wp = (const ulonglong2*)&ws[warp][h][0];
        #pragma unroll
        for (int j = 0; j < 4; j++) {
            const ulonglong2 w2 = wp[j];
            a0[2*j+0] = ffma2(w2.x, xx0, a0[2*j+0]);
            a0[2*j+1] = ffma2(w2.y, xx0, a0[2*j+1]);
            a1[2*j+0] = ffma2(w2.x, xx1, a1[2*j+0]);
            a1[2*j+1] = ffma2(w2.y, xx1, a1[2*j+1]);
        }
    }

    const float inv = 1.0f / (float)(cnt > 0 ? cnt : 1);
    const unsigned long long inv2 = splat2(inv);

    // ---- epilogue: channels 2*lane, 2*lane+1 -> contiguous 64B stores ----
    uint32_t p[16];
    #pragma unroll
    for (int half = 0; half < 2; half++) {
        const unsigned long long* acc = half ? a1 : a0;
        #pragma unroll
        for (int j = 0; j < 8; j++) {
            const float2 s = unpack2(mul2(acc[j], inv2));
            p[half * 8 + j] = pack_f16x2(s.x, s.y);
        }
    }
    uint4* pa = (uint4*)(g_a + (size_t)n * KC2 + (size_t)(2 * lane) * 16);
    #pragma unroll
    for (int q = 0; q < 4; q++)
        pa[q] = make_uint4(p[4*q], p[4*q+1], p[4*q+2], p[4*q+3]);
}

// =============================================================================
// Stage 2 (R11 exactly): single fp16 product out = A x B. BM=128.
// Smem per buffer: A 16K | Bfrag 8K = 24K; x2 = 48 KB.
// Warp w owns m-tile rows [w*16, w*16+16), all 8 n-tiles; 8 MMAs/warp/ks.
// =============================================================================
#define S2_THREADS 256
#define BUFB 24576
#define OFF_BF  16384
#define SM_TOT  (2 * BUFB)

__device__ __forceinline__ void s2_issue(uint32_t sb, int buf, int chunk, int tid,
                                         const char* Apl) {
    const uint32_t base = sb + buf * BUFB;
    #pragma unroll
    for (int i = 0; i < 4; i++) {                 // A: 128 rows x 128B
        const int ch  = i * S2_THREADS + tid;     // 0..1023
        const int rr  = ch >> 3;
        const int c16 = (ch & 7) * 16;
        const uint32_t d = SWZ((uint32_t)(rr * 128 + c16));
        cp16(base + d, Apl + (size_t)rr * 2048 + chunk * 128 + c16);
    }
    #pragma unroll
    for (int i = 0; i < 2; i++) {                 // B frags: 8 KB linear
        const int ch = i * S2_THREADS + tid;      // 0..511
        cp16(base + OFF_BF + ch * 16, (const char*)g_bfrag + ((size_t)chunk * 512 + ch) * 16);
    }
}

__global__ void __launch_bounds__(S2_THREADS) kpconv_stage2(float* __restrict__ out) {
    extern __shared__ __align__(1024) char smem[];
    const uint32_t sb = smem_u32(smem);
    const int tid  = threadIdx.x;
    const int wid  = tid >> 5;
    const int lane = tid & 31;
    const int n0   = blockIdx.x * 128;
    const int m0   = wid * 16;

    const char* Apl = (const char*)(g_a + (size_t)n0 * KC2);

    float d[8][4];
    #pragma unroll
    for (int t = 0; t < 8; t++)
        #pragma unroll
        for (int j = 0; j < 4; j++) d[t][j] = 0.0f;

    const uint32_t arow  = (uint32_t)(m0 + (lane & 15));
    const uint32_t ahalf = (uint32_t)((lane >> 4) * 16);   // bytes

    s2_issue(sb, 0, 0, tid, Apl);
    CP_COMMIT();

    for (int ch = 0; ch < 16; ch++) {
        if (ch + 1 < 16) {
            s2_issue(sb, (ch + 1) & 1, ch + 1, tid, Apl);
            CP_COMMIT();
            CP_WAIT1();
        } else {
            CP_WAIT0();
        }
        __syncthreads();

        const uint32_t base = sb + (ch & 1) * BUFB;
        #pragma unroll
        for (int ks = 0; ks < 4; ks++) {
            const uint32_t aoff = SWZ(arow * 128 + (uint32_t)(ks * 32) + ahalf);
            uint32_t a[4];
            ldsm4(a[0], a[1], a[2], a[3], base + aoff);
            const uint32_t bbase = base + OFF_BF + (uint32_t)(ks * 8 * 32 + lane) * 8;
            #pragma unroll
            for (int nt = 0; nt < 8; nt++) {
                uint2 bf;
                asm volatile("ld.shared.v2.b32 {%0,%1}, [%2];"
                    : "=r"(bf.x), "=r"(bf.y)
                    : "r"(bbase + (uint32_t)(nt * 32 * 8)));
                mma16816(d[nt], a, bf.x, bf.y);
            }
        }
        __syncthreads();
    }

    const int r0 = n0 + m0 + (lane >> 2);
    const int r1 = r0 + 8;
    const int c0 = (lane & 3) * 2;
    #pragma unroll
    for (int nt = 0; nt < 8; nt++) {
        const int c = nt * 8 + c0;
        if (r0 < NQ) *(float2*)(out + (size_t)r0 * ND + c) = make_float2(d[nt][0], d[nt][1]);
        if (r1 < NQ) *(float2*)(out + (size_t)r1 * ND + c) = make_float2(d[nt][2], d[nt][3]);
    }
}

// =============================================================================
extern "C" void kernel_launch(void* const* d_in, const int* in_sizes, int n_in,
                              void* d_out, int out_size) {
    const float* q_pts = (const float*)d_in[0];
    const float* s_pts = (const float*)d_in[1];
    const int*   nbi   = (const int*)  d_in[2];
    const float* x     = (const float*)d_in[3];
    const float* kp    = (const float*)d_in[4];
    const float* W     = (const float*)d_in[5];
    float* out = (float*)d_out;

    cudaFuncSetAttribute(kpconv_stage2, cudaFuncAttributeMaxDynamicSharedMemorySize, SM_TOT);

    prep_x<<<(NMS * NC / 4) / 256, 256>>>(x);
    prep_flags<<<NMS / 16, 256>>>(x);
    prep_w<<<64, 256>>>(W);
    kpconv_stage1<<<NQ / 8, 256>>>(q_pts, s_pts, nbi, kp);
    kpconv_stage2<<<KPAD / 128, S2_THREADS, SM_TOT>>>(out);
}